// round 3
// baseline (speedup 1.0000x reference)
#include <cuda_runtime.h>

// Problem constants
#define W_IMG 512
#define H_IMG 512
#define CCH   3
#define BATCH 32
#define KSZ   32
#define PAD_LO 15            // SAME padding, even kernel: lo=15, hi=16

// Tiling
#define TX 32                // output x per block
#define TY 64                // output y per block
#define NB 4                 // batches per block
#define TP 8                 // y pixels per thread
#define NTHREADS 256
#define ROWS_S  (TX + KSZ - 1)   // 63
#define COLS_S  (TY + KSZ - 1)   // 95
#define PITCH   97               // odd pitch -> conflict-free per-warp row access

#define N_PRED ((size_t)BATCH * W_IMG * H_IMG * CCH)   // 25165824

__device__ double g_loss_sum;

__global__ void init_kernel() { g_loss_sum = 0.0; }

__device__ __forceinline__ unsigned long long pack2(float v) {
    unsigned long long r;
    asm("mov.b64 %0, {%1, %2};" : "=l"(r) : "f"(v), "f"(v));
    return r;
}

__device__ __forceinline__ void fma2(unsigned long long& acc,
                                     unsigned long long a,
                                     unsigned long long b) {
    // packed fp32x2 FMA (sm_100+). ptxas never emits this from C++; PTX only.
    asm("fma.rn.f32x2 %0, %1, %2, %0;" : "+l"(acc) : "l"(a), "l"(b));
}

__device__ __forceinline__ void unpack2(unsigned long long v, float& lo, float& hi) {
    asm("mov.b64 {%0, %1}, %2;" : "=f"(lo), "=f"(hi) : "l"(v));
}

__global__ __launch_bounds__(NTHREADS, 3)
void conv_kernel(const float* __restrict__ img,
                 const float* __restrict__ psf,
                 const float* __restrict__ obs,
                 float* __restrict__ out)
{
    __shared__ float s_img[ROWS_S * PITCH];                 // 24444 B
    __shared__ __align__(16) float s_psf[KSZ * KSZ * NB];   // 16384 B, layout [r][s][b]
    __shared__ float s_red[NTHREADS / 32];

    const int tid = threadIdx.x;
    const int bx  = blockIdx.x;      // 0..127 : (tx*8 + ty)
    const int c   = blockIdx.y;      // channel
    const int bg  = blockIdx.z;      // batch group (NB batches)
    const int ty_ = bx & 7;
    const int tx_ = bx >> 3;
    const int x0  = tx_ * TX;
    const int y0  = ty_ * TY;

    // ---- stage image halo tile (zero-padded) ----
    for (int i = tid; i < ROWS_S * COLS_S; i += NTHREADS) {
        int row = i / COLS_S;
        int col = i - row * COLS_S;
        int gx = x0 - PAD_LO + row;
        int gy = y0 - PAD_LO + col;
        float v = 0.f;
        if ((unsigned)gx < W_IMG && (unsigned)gy < H_IMG)
            v = img[((size_t)gx * H_IMG + gy) * CCH + c];
        s_img[row * PITCH + col] = v;
    }
    // ---- stage PSF for NB batches, channel c : s_psf[(r*32+s)*NB + b] ----
    for (int i = tid; i < KSZ * KSZ * NB; i += NTHREADS) {
        int b  = i >> 10;          // i / (KSZ*KSZ)
        int rs = i & 1023;
        s_psf[rs * NB + b] =
            psf[((size_t)(bg * NB + b) * (KSZ * KSZ) + rs) * CCH + c];
    }
    __syncthreads();

    const int lx  = tid & 31;      // output x within tile (warp = one x-row set)
    const int ly8 = tid >> 5;      // which TP-pixel group along y

    unsigned long long acc2[TP][2];
#pragma unroll
    for (int j = 0; j < TP; ++j) { acc2[j][0] = 0ull; acc2[j][1] = 0ull; }

    const ulonglong2* s_psf2 = reinterpret_cast<const ulonglong2*>(s_psf);

    for (int r = 0; r < KSZ; ++r) {
        const float* rowp = s_img + (lx + r) * PITCH + ly8 * TP;
        const ulonglong2* prow = s_psf2 + r * KSZ;

        // ramp-up: t = 0..6, j <= t
#pragma unroll
        for (int t = 0; t < 7; ++t) {
            unsigned long long v2 = pack2(rowp[t]);
#pragma unroll
            for (int j = 0; j < TP; ++j) {
                if (j <= t) {
                    ulonglong2 p = prow[t - j];
                    fma2(acc2[j][0], v2, p.x);
                    fma2(acc2[j][1], v2, p.y);
                }
            }
        }
        // main: t = 7..31, all 8 j valid (s = t-j in [t-7, t])
#pragma unroll 1
        for (int t = 7; t < KSZ; ++t) {
            unsigned long long v2 = pack2(rowp[t]);
            const ulonglong2* pp = prow + (t - 7);
#pragma unroll
            for (int j = 0; j < TP; ++j) {
                ulonglong2 p = pp[7 - j];       // s = t - j
                fma2(acc2[j][0], v2, p.x);
                fma2(acc2[j][1], v2, p.y);
            }
        }
        // ramp-down: t = 32..38, j >= t-31
#pragma unroll
        for (int t = KSZ; t < KSZ + 7; ++t) {
            unsigned long long v2 = pack2(rowp[t]);
#pragma unroll
            for (int j = 0; j < TP; ++j) {
                if (j >= t - 31) {
                    ulonglong2 p = prow[t - j];
                    fma2(acc2[j][0], v2, p.x);
                    fma2(acc2[j][1], v2, p.y);
                }
            }
        }
    }

    // ---- epilogue: write predicted, fuse squared-error ----
    const int gx    = x0 + lx;
    const int ybase = y0 + ly8 * TP;
    float lsum = 0.f;
#pragma unroll
    for (int b = 0; b < NB; ++b) {
        const int bglob = bg * NB + b;
        const size_t base =
            ((size_t)((size_t)bglob * W_IMG + gx) * H_IMG + ybase) * CCH + c;
#pragma unroll
        for (int j = 0; j < TP; ++j) {
            float lo, hi;
            unpack2(acc2[j][b >> 1], lo, hi);
            float pred = (b & 1) ? hi : lo;
            size_t idx = base + (size_t)j * CCH;
            out[idx] = pred;
            float d = obs[idx] - pred;
            lsum += d * d;
        }
    }

    // block reduction -> one double atomic per block
#pragma unroll
    for (int off = 16; off; off >>= 1)
        lsum += __shfl_xor_sync(0xffffffffu, lsum, off);
    if (lx == 0) s_red[ly8] = lsum;
    __syncthreads();
    if (tid == 0) {
        float bsum = 0.f;
#pragma unroll
        for (int w = 0; w < NTHREADS / 32; ++w) bsum += s_red[w];
        atomicAdd(&g_loss_sum, (double)bsum);
    }
}

__global__ void finalize_kernel(float* out, long long loss_idx) {
    out[loss_idx] = (float)(g_loss_sum / (double)N_PRED);
}

extern "C" void kernel_launch(void* const* d_in, const int* in_sizes, int n_in,
                              void* d_out, int out_size) {
    const float* obs = nullptr;
    const float* img = nullptr;
    const float* psf = nullptr;
    for (int i = 0; i < n_in; ++i) {
        long long n = in_sizes[i];
        if (n == (long long)BATCH * W_IMG * H_IMG * CCH)      obs = (const float*)d_in[i];
        else if (n == (long long)W_IMG * H_IMG * CCH)         img = (const float*)d_in[i];
        else if (n == (long long)BATCH * KSZ * KSZ * CCH)     psf = (const float*)d_in[i];
    }
    float* out = (float*)d_out;

    init_kernel<<<1, 1>>>();
    dim3 grid(128, CCH, BATCH / NB);   // (16 x-tiles * 8 y-tiles, 3 channels, 8 batch groups)
    conv_kernel<<<grid, NTHREADS>>>(img, psf, obs, out);
    finalize_kernel<<<1, 1>>>(out, (long long)out_size - 1);
}

// round 4
// speedup vs baseline: 1.9898x; 1.9898x over previous
#include <cuda_runtime.h>

// Problem constants
#define W_IMG 512
#define H_IMG 512
#define CCH   3
#define BATCH 32
#define KSZ   32
#define PAD_LO 15            // SAME padding, even kernel: lo=15, hi=16

// Tiling
#define TX 32                // output x per block (warp lanes)
#define TY 64                // output y per block
#define NB 4                 // batches per block
#define TP 8                 // y pixels per thread
#define NTHREADS 256
#define ROWS_S  (TX + KSZ - 1)   // 63
#define COLS_S  (TY + KSZ - 1)   // 95
#define PITCH   97               // odd pitch -> conflict-free per-warp row access

#define NBLOCKS (128 * CCH * (BATCH / NB))             // 3072
#define N_PRED  ((size_t)BATCH * W_IMG * H_IMG * CCH)  // 25165824

__device__ double       g_partials[NBLOCKS];
__device__ unsigned int g_done = 0;

__device__ __forceinline__ unsigned long long pack2(float v) {
    unsigned long long r;
    asm("mov.b64 %0, {%1, %2};" : "=l"(r) : "f"(v), "f"(v));
    return r;
}

__device__ __forceinline__ void fma2(unsigned long long& acc,
                                     unsigned long long a,
                                     unsigned long long b) {
    // packed fp32x2 FMA (sm_100+): 2 fp32 MACs per fma-pipe slot. PTX-only.
    asm("fma.rn.f32x2 %0, %1, %2, %0;" : "+l"(acc) : "l"(a), "l"(b));
}

__device__ __forceinline__ void unpack2(unsigned long long v, float& lo, float& hi) {
    asm("mov.b64 {%0, %1}, %2;" : "=f"(lo), "=f"(hi) : "l"(v));
}

__global__ __launch_bounds__(NTHREADS, 2)
void conv_kernel(const float* __restrict__ img,
                 const float* __restrict__ psf,
                 const float* __restrict__ obs,
                 float* __restrict__ out,
                 long long loss_idx)
{
    __shared__ float s_img[ROWS_S * PITCH];                 // 24444 B
    __shared__ __align__(16) float s_psf[KSZ * KSZ * NB];   // 16384 B, layout [r][s][b]
    __shared__ float s_red[NTHREADS / 32];
    __shared__ int   s_last;
    __shared__ double s_dred[NTHREADS / 32];

    const int tid = threadIdx.x;
    const int bx  = blockIdx.x;      // 0..127 : (tx*8 + ty)
    const int c   = blockIdx.y;      // channel
    const int bg  = blockIdx.z;      // batch group (NB batches)
    const int ty_ = bx & 7;
    const int tx_ = bx >> 3;
    const int x0  = tx_ * TX;
    const int y0  = ty_ * TY;

    // ---- stage image halo tile (zero-padded) ----
    for (int i = tid; i < ROWS_S * COLS_S; i += NTHREADS) {
        int row = i / COLS_S;
        int col = i - row * COLS_S;
        int gx = x0 - PAD_LO + row;
        int gy = y0 - PAD_LO + col;
        float v = 0.f;
        if ((unsigned)gx < W_IMG && (unsigned)gy < H_IMG)
            v = img[((size_t)gx * H_IMG + gy) * CCH + c];
        s_img[row * PITCH + col] = v;
    }
    // ---- stage PSF for NB batches, channel c : s_psf[(r*32+s)*NB + b] ----
    for (int i = tid; i < KSZ * KSZ * NB; i += NTHREADS) {
        int b  = i >> 10;          // i / (KSZ*KSZ)
        int rs = i & 1023;
        s_psf[rs * NB + b] =
            psf[((size_t)(bg * NB + b) * (KSZ * KSZ) + rs) * CCH + c];
    }
    __syncthreads();

    const int lx  = tid & 31;      // output x within tile
    const int ly8 = tid >> 5;      // which TP-pixel group along y

    unsigned long long acc2[TP][2];
#pragma unroll
    for (int j = 0; j < TP; ++j) { acc2[j][0] = 0ull; acc2[j][1] = 0ull; }

    const ulonglong2* s_psf2 = reinterpret_cast<const ulonglong2*>(s_psf);

#pragma unroll 1
    for (int r = 0; r < KSZ; ++r) {
        const float* rowp = s_img + (lx + r) * PITCH + ly8 * TP;
        const ulonglong2* prow = s_psf2 + r * KSZ;

        // sliding register window over PSF taps: Wx/Wy hold s in [t-7, t]
        unsigned long long Wx[8], Wy[8];
        ulonglong2 pnext = prow[0];
        float      vnext = rowp[0];

#pragma unroll
        for (int t = 0; t < KSZ + 7; ++t) {
            unsigned long long v2 = pack2(vnext);
            if (t + 1 < KSZ + 7) vnext = rowp[t + 1];   // prefetch image pixel
            if (t < KSZ) {
                Wx[t & 7] = pnext.x;
                Wy[t & 7] = pnext.y;
                if (t + 1 < KSZ) pnext = prow[t + 1];   // prefetch PSF quad
            }
#pragma unroll
            for (int j = 0; j < TP; ++j) {
                if (j <= t && j >= t - 31) {            // compile-time after unroll
                    const int s = t - j;
                    fma2(acc2[j][0], v2, Wx[s & 7]);
                    fma2(acc2[j][1], v2, Wy[s & 7]);
                }
            }
        }
    }

    // ---- epilogue: write predicted, fuse squared-error ----
    const int gx    = x0 + lx;
    const int ybase = y0 + ly8 * TP;
    float lsum = 0.f;
#pragma unroll
    for (int b = 0; b < NB; ++b) {
        const int bglob = bg * NB + b;
        const size_t base =
            ((size_t)((size_t)bglob * W_IMG + gx) * H_IMG + ybase) * CCH + c;
#pragma unroll
        for (int j = 0; j < TP; ++j) {
            float lo, hi;
            unpack2(acc2[j][b >> 1], lo, hi);
            float pred = (b & 1) ? hi : lo;
            size_t idx = base + (size_t)j * CCH;
            out[idx] = pred;
            float d = obs[idx] - pred;
            lsum += d * d;
        }
    }

    // block reduction of squared error
#pragma unroll
    for (int off = 16; off; off >>= 1)
        lsum += __shfl_xor_sync(0xffffffffu, lsum, off);
    if (lx == 0) s_red[ly8] = lsum;
    __syncthreads();

    const int lin = bx + gridDim.x * (c + CCH * bg);
    if (tid == 0) {
        float bsum = 0.f;
#pragma unroll
        for (int w = 0; w < NTHREADS / 32; ++w) bsum += s_red[w];
        g_partials[lin] = (double)bsum;
        __threadfence();
        unsigned prev = atomicAdd(&g_done, 1u);
        s_last = (prev == NBLOCKS - 1);
    }
    __syncthreads();

    // last finished block reduces partials -> loss, resets counter
    if (s_last) {
        double d = 0.0;
        for (int i = tid; i < NBLOCKS; i += NTHREADS) d += g_partials[i];
#pragma unroll
        for (int off = 16; off; off >>= 1)
            d += __shfl_xor_sync(0xffffffffu, d, off);
        if (lx == 0) s_dred[ly8] = d;
        __syncthreads();
        if (tid == 0) {
            double tot = 0.0;
#pragma unroll
            for (int w = 0; w < NTHREADS / 32; ++w) tot += s_dred[w];
            out[loss_idx] = (float)(tot / (double)N_PRED);
            g_done = 0;   // self-reset: deterministic across graph replays
        }
    }
}

extern "C" void kernel_launch(void* const* d_in, const int* in_sizes, int n_in,
                              void* d_out, int out_size) {
    const float* obs = nullptr;
    const float* img = nullptr;
    const float* psf = nullptr;
    for (int i = 0; i < n_in; ++i) {
        long long n = in_sizes[i];
        if (n == (long long)BATCH * W_IMG * H_IMG * CCH)      obs = (const float*)d_in[i];
        else if (n == (long long)W_IMG * H_IMG * CCH)         img = (const float*)d_in[i];
        else if (n == (long long)BATCH * KSZ * KSZ * CCH)     psf = (const float*)d_in[i];
    }
    float* out = (float*)d_out;

    dim3 grid(128, CCH, BATCH / NB);   // 3072 blocks
    conv_kernel<<<grid, NTHREADS>>>(img, psf, obs, out,
                                    (long long)out_size - 1);
}

// round 5
// speedup vs baseline: 2.0280x; 1.0192x over previous
#include <cuda_runtime.h>

// Problem constants
#define W_IMG 512
#define H_IMG 512
#define CCH   3
#define BATCH 32
#define KSZ   32
#define PAD_LO 15            // SAME padding, even kernel: lo=15, hi=16

// Tiling
#define TX 32                // output x per block (warp lanes)
#define TY 64                // output y per block
#define NB 4                 // batches per block
#define TP 8                 // y pixels per thread
#define NTHREADS 256
#define ROWS_S  (TX + KSZ - 1)   // 63
#define COLS_S  (TY + KSZ - 1)   // 95
#define PITCH   97               // odd pitch -> conflict-free per-warp row access

#define NBLOCKS (128 * CCH * (BATCH / NB))             // 3072
#define N_PRED  ((size_t)BATCH * W_IMG * H_IMG * CCH)  // 25165824

__device__ double       g_partials[NBLOCKS];
__device__ unsigned int g_done = 0;

__device__ __forceinline__ unsigned long long pack2(float v) {
    unsigned long long r;
    asm("mov.b64 %0, {%1, %2};" : "=l"(r) : "f"(v), "f"(v));
    return r;
}

__device__ __forceinline__ void fma2(unsigned long long& acc,
                                     unsigned long long a,
                                     unsigned long long b) {
    // packed fp32x2 FMA (sm_100+): 2 fp32 MACs per fma-pipe slot. PTX-only.
    asm("fma.rn.f32x2 %0, %1, %2, %0;" : "+l"(acc) : "l"(a), "l"(b));
}

__device__ __forceinline__ void unpack2(unsigned long long v, float& lo, float& hi) {
    asm("mov.b64 {%0, %1}, %2;" : "=f"(lo), "=f"(hi) : "l"(v));
}

__global__ __launch_bounds__(NTHREADS, 3)
void conv_kernel(const float* __restrict__ img,
                 const float* __restrict__ psf,
                 const float* __restrict__ obs,
                 float* __restrict__ out,
                 long long loss_idx)
{
    __shared__ float s_img[ROWS_S * PITCH];                 // 24444 B
    __shared__ __align__(16) float s_psf[KSZ * KSZ * NB];   // 16384 B, layout [r][s][b]
    __shared__ float s_red[NTHREADS / 32];
    __shared__ int   s_last;
    __shared__ double s_dred[NTHREADS / 32];

    const int tid = threadIdx.x;
    const int bx  = blockIdx.x;      // 0..127 : (tx*8 + ty)
    const int c   = blockIdx.y;      // channel
    const int bg  = blockIdx.z;      // batch group (NB batches)
    const int ty_ = bx & 7;
    const int tx_ = bx >> 3;
    const int x0  = tx_ * TX;
    const int y0  = ty_ * TY;

    // ---- stage image halo tile (zero-padded) ----
    for (int i = tid; i < ROWS_S * COLS_S; i += NTHREADS) {
        int row = i / COLS_S;
        int col = i - row * COLS_S;
        int gx = x0 - PAD_LO + row;
        int gy = y0 - PAD_LO + col;
        float v = 0.f;
        if ((unsigned)gx < W_IMG && (unsigned)gy < H_IMG)
            v = img[((size_t)gx * H_IMG + gy) * CCH + c];
        s_img[row * PITCH + col] = v;
    }
    // ---- stage PSF for NB batches, channel c : s_psf[(r*32+s)*NB + b] ----
    for (int i = tid; i < KSZ * KSZ * NB; i += NTHREADS) {
        int b  = i >> 10;          // i / (KSZ*KSZ)
        int rs = i & 1023;
        s_psf[rs * NB + b] =
            psf[((size_t)(bg * NB + b) * (KSZ * KSZ) + rs) * CCH + c];
    }
    __syncthreads();

    const int lx  = tid & 31;      // output x within tile
    const int ly8 = tid >> 5;      // which TP-pixel group along y

    unsigned long long acc2[TP][2];
#pragma unroll
    for (int j = 0; j < TP; ++j) { acc2[j][0] = 0ull; acc2[j][1] = 0ull; }

    const ulonglong2* s_psf2 = reinterpret_cast<const ulonglong2*>(s_psf);

#pragma unroll 1
    for (int r = 0; r < KSZ; ++r) {
        const float* rowp = s_img + (lx + r) * PITCH + ly8 * TP;
        const ulonglong2* prow = s_psf2 + r * KSZ;

        // 8-deep sliding window over IMAGE pixels (packed fp32x2 duplicates).
        // At step s it holds v[s .. s+7]; every step is a dense 16-FFMA2 burst.
        unsigned long long vwin[8];
#pragma unroll
        for (int i = 0; i < 7; ++i) vwin[i] = pack2(rowp[i]);

#pragma unroll
        for (int s = 0; s < KSZ; ++s) {
            vwin[(s + 7) & 7] = pack2(rowp[s + 7]);   // slide window
            ulonglong2 p = prow[s];                   // broadcast: 4-batch tap quad
#pragma unroll
            for (int j = 0; j < TP; ++j) {
                const unsigned long long v2 = vwin[(s + j) & 7];
                fma2(acc2[j][0], v2, p.x);
                fma2(acc2[j][1], v2, p.y);
            }
        }
    }

    // ---- epilogue: write predicted, fuse squared-error ----
    const int gx    = x0 + lx;
    const int ybase = y0 + ly8 * TP;
    float lsum = 0.f;
#pragma unroll
    for (int b = 0; b < NB; ++b) {
        const int bglob = bg * NB + b;
        const size_t base =
            ((size_t)((size_t)bglob * W_IMG + gx) * H_IMG + ybase) * CCH + c;
#pragma unroll
        for (int j = 0; j < TP; ++j) {
            float lo, hi;
            unpack2(acc2[j][b >> 1], lo, hi);
            float pred = (b & 1) ? hi : lo;
            size_t idx = base + (size_t)j * CCH;
            out[idx] = pred;
            float d = obs[idx] - pred;
            lsum += d * d;
        }
    }

    // block reduction of squared error
#pragma unroll
    for (int off = 16; off; off >>= 1)
        lsum += __shfl_xor_sync(0xffffffffu, lsum, off);
    if (lx == 0) s_red[ly8] = lsum;
    __syncthreads();

    const int lin = bx + gridDim.x * (c + CCH * bg);
    if (tid == 0) {
        float bsum = 0.f;
#pragma unroll
        for (int w = 0; w < NTHREADS / 32; ++w) bsum += s_red[w];
        g_partials[lin] = (double)bsum;
        __threadfence();
        unsigned prev = atomicAdd(&g_done, 1u);
        s_last = (prev == NBLOCKS - 1);
    }
    __syncthreads();

    // last finished block reduces partials -> loss, resets counter
    if (s_last) {
        double d = 0.0;
        for (int i = tid; i < NBLOCKS; i += NTHREADS) d += g_partials[i];
#pragma unroll
        for (int off = 16; off; off >>= 1)
            d += __shfl_xor_sync(0xffffffffu, d, off);
        if (lx == 0) s_dred[ly8] = d;
        __syncthreads();
        if (tid == 0) {
            double tot = 0.0;
#pragma unroll
            for (int w = 0; w < NTHREADS / 32; ++w) tot += s_dred[w];
            out[loss_idx] = (float)(tot / (double)N_PRED);
            g_done = 0;   // self-reset: deterministic across graph replays
        }
    }
}

extern "C" void kernel_launch(void* const* d_in, const int* in_sizes, int n_in,
                              void* d_out, int out_size) {
    const float* obs = nullptr;
    const float* img = nullptr;
    const float* psf = nullptr;
    for (int i = 0; i < n_in; ++i) {
        long long n = in_sizes[i];
        if (n == (long long)BATCH * W_IMG * H_IMG * CCH)      obs = (const float*)d_in[i];
        else if (n == (long long)W_IMG * H_IMG * CCH)         img = (const float*)d_in[i];
        else if (n == (long long)BATCH * KSZ * KSZ * CCH)     psf = (const float*)d_in[i];
    }
    float* out = (float*)d_out;

    dim3 grid(128, CCH, BATCH / NB);   // 3072 blocks
    conv_kernel<<<grid, NTHREADS>>>(img, psf, obs, out,
                                    (long long)out_size - 1);
}

// round 8
// speedup vs baseline: 3.4292x; 1.6910x over previous
#include <cuda_runtime.h>
#include <cstdint>

// ---------------- problem constants ----------------
#define W_IMG 512
#define H_IMG 512
#define CCH   3
#define BATCH 32
#define KSZ   32
#define PAD_LO 15            // SAME padding, even kernel: lo=15, hi=16

#define MTILE 128            // y-pixels per CTA (GEMM M)
#define NTH   128            // 4 warps
#define YTILES (H_IMG / MTILE)                // 4
#define NBLOCKS (YTILES * W_IMG * CCH)        // 6144
#define N_PRED ((size_t)BATCH * W_IMG * H_IMG * CCH)

// smem union (u32 units):
//   staging buf p: raw[160] @ RAW_OFF(p), B tf32 [32 k rows x pitch 40] @ B_OFF(p)
//   epilogue:      s_d [32 n x pitch 132] floats, reuses same storage
#define RAWLEN 160
#define BPITCH 40
#define BUFLEN (RAWLEN + KSZ * BPITCH)   // 1440
#define RAW_OFF(p) ((p) * BUFLEN)
#define B_OFF(p)   ((p) * BUFLEN + RAWLEN)
#define DPITCH 132
#define SMEM_U32 (BATCH * DPITCH)        // 4224 >= 2*BUFLEN (2880)

__device__ double       g_partials[NBLOCKS];
__device__ unsigned int g_done = 0;

static __device__ __forceinline__ uint32_t f2tf(float v) {
    uint32_t r;
    asm("cvt.rna.tf32.f32 %0, %1;" : "=r"(r) : "f"(v));
    return r;
}

// D(16x8,f32) += A(16x8,tf32,row) * B(8x8,tf32,col)
static __device__ __forceinline__ void mma_tf32(float* d, const uint32_t* a,
                                                const uint32_t* b) {
    asm volatile(
        "mma.sync.aligned.m16n8k8.row.col.f32.tf32.tf32.f32 "
        "{%0,%1,%2,%3}, {%4,%5,%6,%7}, {%8,%9}, {%0,%1,%2,%3};"
        : "+f"(d[0]), "+f"(d[1]), "+f"(d[2]), "+f"(d[3])
        : "r"(a[0]), "r"(a[1]), "r"(a[2]), "r"(a[3]), "r"(b[0]), "r"(b[1]));
}

__global__ __launch_bounds__(NTH)
void conv_mma_kernel(const float* __restrict__ img,
                     const float* __restrict__ psf,
                     const float* __restrict__ obs,
                     float* __restrict__ out,
                     long long loss_idx)
{
    __shared__ uint32_t s_u[SMEM_U32];
    __shared__ float  s_red[NTH / 32];
    __shared__ double s_dred[NTH / 32];
    __shared__ int    s_last;

    const int tid   = threadIdx.x;
    const int wid   = tid >> 5;
    const int lane  = tid & 31;
    const int ytile = blockIdx.x;
    const int x     = blockIdx.y;
    const int c     = blockIdx.z;
    const int y0    = ytile * MTILE;

    const int g  = lane >> 2;        // groupID (row within fragment)
    const int t4 = lane & 3;         // threadID_in_group (col/k within fragment)

    // ---- accumulators: warp w owns rows [32w, 32w+32), all 32 batches ----
    float d[2][4][4];
#pragma unroll
    for (int mt = 0; mt < 2; ++mt)
#pragma unroll
        for (int nt = 0; nt < 4; ++nt)
#pragma unroll
            for (int i = 0; i < 4; ++i) d[mt][nt][i] = 0.f;

    // ---- staging load (gmem -> regs) for PSF row r ----
    float rv0, rv1, bv[8];
    auto load_stage = [&](int r) {
        const int gx = x + r - PAD_LO;
        // raw image row, 160 values, zero padded
        {
            int i0 = tid, i1 = tid + NTH;
            int gy0 = y0 - PAD_LO + i0;
            int gy1 = y0 - PAD_LO + i1;
            rv0 = 0.f; rv1 = 0.f;
            if ((unsigned)gx < W_IMG) {
                const float* rowp = img + ((size_t)gx * H_IMG) * CCH + c;
                if ((unsigned)gy0 < H_IMG) rv0 = rowp[(size_t)gy0 * CCH];
                if (i1 < RAWLEN && (unsigned)gy1 < H_IMG) rv1 = rowp[(size_t)gy1 * CCH];
            }
        }
        // B chunk: psf[b, r, s, c], 1024 values -> 8 per thread
#pragma unroll
        for (int j = 0; j < 8; ++j) {
            int e = tid + j * NTH;
            int b = e >> 5, s = e & 31;
            bv[j] = psf[((size_t)(b * KSZ + r) * KSZ + s) * CCH + c];
        }
    };
    // ---- staging store (regs -> smem, tf32-converted) into buffer p ----
    auto store_stage = [&](int p) {
        uint32_t* raw = s_u + RAW_OFF(p);
        uint32_t* Bs  = s_u + B_OFF(p);
        raw[tid] = f2tf(rv0);
        if (tid + NTH < RAWLEN) raw[tid + NTH] = f2tf(rv1);
#pragma unroll
        for (int j = 0; j < 8; ++j) {
            int e = tid + j * NTH;
            int b = e >> 5, s = e & 31;
            Bs[s * BPITCH + b] = f2tf(bv[j]);   // [k=s][n=b], conflict-free pitch
        }
    };

    load_stage(0);
    store_stage(0);
    __syncthreads();

    // ---------------- main loop over PSF rows ----------------
#pragma unroll 1
    for (int r = 0; r < KSZ; ++r) {
        if (r + 1 < KSZ) load_stage(r + 1);     // issue LDGs early

        const uint32_t* raw = s_u + RAW_OFF(r & 1);
        const uint32_t* Bs  = s_u + B_OFF(r & 1);
        const int abase = 32 * wid + g + t4;    // Toeplitz: A[m][s] = raw[m+s]
        const int bbase = t4 * BPITCH + g;

#pragma unroll
        for (int k8 = 0; k8 < 4; ++k8) {
            uint32_t a[2][4];
#pragma unroll
            for (int mt = 0; mt < 2; ++mt) {
                const int S = abase + k8 * 8 + mt * 16;
                a[mt][0] = raw[S];          // (row g,   col t4)
                a[mt][1] = raw[S + 8];      // (row g+8, col t4)
                a[mt][2] = raw[S + 4];      // (row g,   col t4+4)
                a[mt][3] = raw[S + 12];     // (row g+8, col t4+4)
            }
            uint32_t b[4][2];
#pragma unroll
            for (int nt = 0; nt < 4; ++nt) {
                const int off = bbase + k8 * 8 * BPITCH + nt * 8;
                b[nt][0] = Bs[off];               // (k = t4,   n = g)
                b[nt][1] = Bs[off + 4 * BPITCH];  // (k = t4+4, n = g)
            }
#pragma unroll
            for (int mt = 0; mt < 2; ++mt)
#pragma unroll
                for (int nt = 0; nt < 4; ++nt)
                    mma_tf32(d[mt][nt], a[mt], b[nt]);
        }

        if (r + 1 < KSZ) store_stage((r + 1) & 1);
        __syncthreads();
    }

    // ---------------- epilogue: D -> smem transpose -> gmem + loss ----------------
    // (barrier above guarantees staging reads are done; reuse s_u as s_d[n][y])
#pragma unroll
    for (int mt = 0; mt < 2; ++mt)
#pragma unroll
        for (int nt = 0; nt < 4; ++nt)
#pragma unroll
            for (int i = 0; i < 4; ++i) {
                const int n = nt * 8 + 2 * t4 + (i & 1);
                const int y = 32 * wid + 16 * mt + g + ((i >> 1) ? 8 : 0);
                s_u[n * DPITCH + y] = __float_as_uint(d[mt][nt][i]);
            }
    __syncthreads();

    // thread -> (batch b = tid/4, y-quarter q = tid%4), 32 consecutive y each
    const int bb = tid >> 2;
    const int yq = tid & 3;
    const uint32_t* drow = s_u + bb * DPITCH + yq * 32;
    const size_t obase =
        ((size_t)((size_t)bb * W_IMG + x) * H_IMG + (y0 + yq * 32)) * CCH + c;
    float lsum = 0.f;
#pragma unroll
    for (int i = 0; i < 32; ++i) {
        float p = __uint_as_float(drow[i]);
        size_t idx = obase + (size_t)i * CCH;
        out[idx] = p;
        float dd = obs[idx] - p;
        lsum += dd * dd;
    }

    // block reduce loss
#pragma unroll
    for (int off = 16; off; off >>= 1)
        lsum += __shfl_xor_sync(0xffffffffu, lsum, off);
    if (lane == 0) s_red[wid] = lsum;
    __syncthreads();

    const int lin = ytile + YTILES * (x + W_IMG * c);
    if (tid == 0) {
        float bsum = 0.f;
#pragma unroll
        for (int w = 0; w < NTH / 32; ++w) bsum += s_red[w];
        g_partials[lin] = (double)bsum;
        __threadfence();
        unsigned prev = atomicAdd(&g_done, 1u);
        s_last = (prev == NBLOCKS - 1);
    }
    __syncthreads();

    if (s_last) {
        double dsum = 0.0;
        for (int i = tid; i < NBLOCKS; i += NTH) dsum += g_partials[i];
#pragma unroll
        for (int off = 16; off; off >>= 1)
            dsum += __shfl_xor_sync(0xffffffffu, dsum, off);
        if (lane == 0) s_dred[wid] = dsum;
        __syncthreads();
        if (tid == 0) {
            double tot = 0.0;
#pragma unroll
            for (int w = 0; w < NTH / 32; ++w) tot += s_dred[w];
            out[loss_idx] = (float)(tot / (double)N_PRED);
            g_done = 0;   // self-reset: deterministic across graph replays
        }
    }
}

extern "C" void kernel_launch(void* const* d_in, const int* in_sizes, int n_in,
                              void* d_out, int out_size) {
    const float* obs = nullptr;
    const float* img = nullptr;
    const float* psf = nullptr;
    for (int i = 0; i < n_in; ++i) {
        long long n = in_sizes[i];
        if (n == (long long)BATCH * W_IMG * H_IMG * CCH)      obs = (const float*)d_in[i];
        else if (n == (long long)W_IMG * H_IMG * CCH)         img = (const float*)d_in[i];
        else if (n == (long long)BATCH * KSZ * KSZ * CCH)     psf = (const float*)d_in[i];
    }
    float* out = (float*)d_out;

    dim3 grid(YTILES, W_IMG, CCH);   // 6144 CTAs
    conv_mma_kernel<<<grid, NTH>>>(img, psf, obs, out, (long long)out_size - 1);
}